// round 11
// baseline (speedup 1.0000x reference)
#include <cuda_runtime.h>

#define T_DIM 32
#define C_DIM 512
#define H_DIM 56
#define W_DIM 56
#define EPSF  1e-6f
#define NPAIR (T_DIM * H_DIM)   // 1792 (t,h) pairs
#define GRID1 (NPAIR / 2)       // 896 blocks, 2 pairs each

// Packed (lin, sq) pairs.
__device__ float2 g_H[T_DIM * H_DIM];            // H-axis finals
__device__ float2 g_pW[T_DIM * H_DIM * W_DIM];   // W partials per (t,h)
__device__ float2 g_W[T_DIM * W_DIM];            // W finals (per-t fold)
__device__ unsigned int g_tickT[T_DIM];          // per-t tickets (zero-init, self-reset)
__device__ unsigned int g_ticket;                // global ticket (zero-init, self-reset)

__global__ __launch_bounds__(224, 9)             // force <=32 regs for the streamer
void fused_kernel(const float* __restrict__ x, float* __restrict__ out)
{
    const int tid  = threadIdx.x;
    const int q    = tid % 14;
    const int r0   = tid / 14;
    const int wid  = tid >> 5;
    const int lane = tid & 31;
    const int stride4 = (H_DIM * W_DIM) / 4;     // 784 float4 per channel

    __shared__ float sbuf[224 * 8];              // reused by every phase
    __shared__ unsigned int s_cnt;

    int t_of[2];

    // ================= Phase 1: streaming (R8 layout, proven) =================
    #pragma unroll
    for (int pp = 0; pp < 2; ++pp) {
        const int p = blockIdx.x + pp * GRID1;
        const int t = p / H_DIM;
        const int h = p % H_DIM;
        t_of[pp] = t;

        const float4* __restrict__ base =
            (const float4*)(x + ((size_t)t * C_DIM * H_DIM + (size_t)h) * W_DIM);

        float linh = 0.f, sqh = 0.f;
        float lw0 = 0.f, lw1 = 0.f, lw2 = 0.f, lw3 = 0.f;
        float sw0 = 0.f, sw1 = 0.f, sw2 = 0.f, sw3 = 0.f;

        #pragma unroll 4
        for (int c = r0; c < C_DIM; c += 16) {
            float4 v = __ldcs(&base[(size_t)c * stride4 + q]);
            linh += v.x + v.y + v.z + v.w;
            sqh  += v.x * v.x + v.y * v.y + v.z * v.z + v.w * v.w;
            lw0 += v.x;  sw0 += v.x * v.x;
            lw1 += v.y;  sw1 += v.y * v.y;
            lw2 += v.z;  sw2 += v.z * v.z;
            lw3 += v.w;  sw3 += v.w * v.w;
        }

        // H reduction: shfl in warp, thread 0 folds 7 warps
        float a = linh, b = sqh;
        #pragma unroll
        for (int off = 16; off > 0; off >>= 1) {
            a += __shfl_down_sync(0xffffffffu, a, off);
            b += __shfl_down_sync(0xffffffffu, b, off);
        }
        if (lane == 0) { sbuf[wid] = a; sbuf[8 + wid] = b; }
        __syncthreads();
        if (tid == 0) {
            float la = 0.f, lb = 0.f;
            #pragma unroll
            for (int i = 0; i < 7; ++i) { la += sbuf[i]; lb += sbuf[8 + i]; }
            g_H[t * H_DIM + h] = make_float2(la, lb);
        }
        __syncthreads();

        // W partials: park 8 values, 56 threads gather
        float* my = &sbuf[tid * 8];
        my[0] = lw0; my[1] = lw1; my[2] = lw2; my[3] = lw3;
        my[4] = sw0; my[5] = sw1; my[6] = sw2; my[7] = sw3;
        __syncthreads();

        if (tid < W_DIM) {
            const int qq = tid >> 2;
            const int ii = tid & 3;
            float la = 0.f, lb = 0.f;
            #pragma unroll
            for (int r = 0; r < 16; ++r) {
                const float* src = &sbuf[(r * 14 + qq) * 8];
                la += src[ii];
                lb += src[4 + ii];
            }
            g_pW[(t * H_DIM + h) * W_DIM + tid] = make_float2(la, lb);
        }
        __syncthreads();
    }

    __threadfence();
    __syncthreads();

    // ============ Phase 2: per-t fold (56th block for each t does it) ============
    float2* sb2 = (float2*)sbuf;
    #pragma unroll
    for (int pp = 0; pp < 2; ++pp) {
        const int t = t_of[pp];
        if (tid == 0) s_cnt = atomicAdd(&g_tickT[t], 1u);
        __syncthreads();
        if (s_cnt == H_DIM - 1) {                   // block-uniform
            // 224 threads = 56 w x 4 h-quarters, each folds 14 h
            const int w  = tid % W_DIM;
            const int hq = tid / W_DIM;
            float a = 0.f, b = 0.f;
            for (int k = 0; k < 14; ++k) {
                float2 v = __ldcg(&g_pW[(t * H_DIM + hq * 14 + k) * W_DIM + w]);
                a += v.x; b += v.y;
            }
            sb2[tid] = make_float2(a, b);
            __syncthreads();
            if (tid < W_DIM) {
                float2 v0 = sb2[tid],       v1 = sb2[tid + 56];
                float2 v2 = sb2[tid + 112], v3 = sb2[tid + 168];
                g_W[t * W_DIM + tid] =
                    make_float2(v0.x + v1.x + v2.x + v3.x,
                                v0.y + v1.y + v2.y + v3.y);
            }
            if (tid == 0) g_tickT[t] = 0;           // deterministic reset
            __syncthreads();
        }
        __syncthreads();                             // s_cnt reuse safety
    }

    __threadfence();
    __syncthreads();

    // ================= Phase 3: global last block -> epilogue =================
    __shared__ unsigned int s_last;
    if (tid == 0) s_last = atomicAdd(&g_ticket, 1u);
    __syncthreads();
    if (s_last != GRID1 - 1) return;
    if (tid == 0) g_ticket = 0;                      // deterministic reset
    __threadfence();
    __syncthreads();

    __shared__ float shS[64];
    if (tid < 64) {
        const int t  = tid & 31;
        const int ax = tid >> 5;                     // 0 = H, 1 = W
        const float2* __restrict__ s = (ax ? g_W : g_H) + t * 56;

        const float n_other = (float)(C_DIM) * 56.f; // 28672
        float total = 0.f;

        float csq = 0.f, clin = 0.f;
        for (int i = 55; i >= 0; --i) {              // suffix slices [i:]
            float2 v = __ldcg(&s[i]);
            clin += v.x;
            csq  += v.y;
            float n = n_other * (float)(56 - i);
            total += sqrtf(csq + 2.f * EPSF * clin + (EPSF * EPSF) * n) + EPSF;
        }
        csq = 0.f; clin = 0.f;
        for (int i = 0; i < 56; ++i) {               // prefix slices [:j+1]
            float2 v = __ldcg(&s[i]);
            clin += v.x;
            csq  += v.y;
            float n = n_other * (float)(i + 1);
            total += sqrtf(csq + 2.f * EPSF * clin + (EPSF * EPSF) * n) + EPSF;
        }
        shS[tid] = total;
    }
    __syncthreads();
    if (tid < 32) {
        float v = shS[tid] + shS[tid + 32];
        #pragma unroll
        for (int off = 16; off > 0; off >>= 1)
            v += __shfl_down_sync(0xffffffffu, v, off);
        if (tid == 0) out[0] = v / 128.f;            // / (T=32 * 4 losses)
    }
}

// ---------------------------------------------------------------------------
extern "C" void kernel_launch(void* const* d_in, const int* in_sizes, int n_in,
                              void* d_out, int out_size)
{
    const float* x = (const float*)d_in[0];
    float* out = (float*)d_out;
    (void)in_sizes; (void)n_in; (void)out_size;

    fused_kernel<<<GRID1, 224>>>(x, out);
}

// round 17
// speedup vs baseline: 1.4944x; 1.4944x over previous
#include <cuda_runtime.h>

#define T_DIM 32
#define C_DIM 512
#define H_DIM 56
#define W_DIM 56
#define EPSF  1e-6f
#define NPAIR (T_DIM * H_DIM)   // 1792 (t,h) pairs
#define GRID1 (NPAIR / 2)       // 896 blocks, 2 pairs each -> one even wave
#define FPSCALE 16777216.0f     // 2^24 fixed-point scale
#define FPINV   (1.0f / 16777216.0f)

// H-axis finals (block-exclusive plain stores)
__device__ float2 g_H[T_DIM * H_DIM];
// W-axis fixed-point accumulators (zero-init at load; epilogue resets -> every
// launch starts from zero; integer adds are associative -> deterministic)
__device__ unsigned long long g_WIlin[T_DIM * W_DIM];
__device__ unsigned long long g_WIsq [T_DIM * W_DIM];

// ---------------------------------------------------------------------------
// Kernel 1: stream the tensor once (R8 body, proven regs=32 / occ 82%).
// 896 blocks x 224 threads, 2 (t,h) pairs each, __ldcs evict-first loads.
// W partials are committed via deterministic int64 atomics.
// ---------------------------------------------------------------------------
__global__ __launch_bounds__(224) void reduce_kernel(const float* __restrict__ x)
{
    const int tid = threadIdx.x;
    const int q   = tid % 14;
    const int r0  = tid / 14;
    const int wid  = tid >> 5;
    const int lane = tid & 31;
    const int stride4 = (H_DIM * W_DIM) / 4;  // 784 float4 per channel

    __shared__ float sbuf[224 * 8];

    #pragma unroll
    for (int pp = 0; pp < 2; ++pp) {
        const int p = blockIdx.x + pp * GRID1;
        const int t = p / H_DIM;
        const int h = p % H_DIM;

        const float4* __restrict__ base =
            (const float4*)(x + ((size_t)t * C_DIM * H_DIM + (size_t)h) * W_DIM);

        float linh = 0.f, sqh = 0.f;
        float lw0 = 0.f, lw1 = 0.f, lw2 = 0.f, lw3 = 0.f;
        float sw0 = 0.f, sw1 = 0.f, sw2 = 0.f, sw3 = 0.f;

        #pragma unroll 4
        for (int c = r0; c < C_DIM; c += 16) {
            float4 v = __ldcs(&base[(size_t)c * stride4 + q]);
            linh += v.x + v.y + v.z + v.w;
            sqh  += v.x * v.x + v.y * v.y + v.z * v.z + v.w * v.w;
            lw0 += v.x;  sw0 += v.x * v.x;
            lw1 += v.y;  sw1 += v.y * v.y;
            lw2 += v.z;  sw2 += v.z * v.z;
            lw3 += v.w;  sw3 += v.w * v.w;
        }

        // H reduction: shfl in warp, thread 0 folds 7 warps
        float a = linh, b = sqh;
        #pragma unroll
        for (int off = 16; off > 0; off >>= 1) {
            a += __shfl_down_sync(0xffffffffu, a, off);
            b += __shfl_down_sync(0xffffffffu, b, off);
        }
        if (lane == 0) { sbuf[wid] = a; sbuf[8 + wid] = b; }
        __syncthreads();
        if (tid == 0) {
            float la = 0.f, lb = 0.f;
            #pragma unroll
            for (int i = 0; i < 7; ++i) { la += sbuf[i]; lb += sbuf[8 + i]; }
            g_H[t * H_DIM + h] = make_float2(la, lb);
        }
        __syncthreads();

        // W partials: park 8 values, 56 threads gather + atomic-commit
        float* my = &sbuf[tid * 8];
        my[0] = lw0; my[1] = lw1; my[2] = lw2; my[3] = lw3;
        my[4] = sw0; my[5] = sw1; my[6] = sw2; my[7] = sw3;
        __syncthreads();

        if (tid < W_DIM) {
            const int qq = tid >> 2;
            const int ii = tid & 3;
            float la = 0.f, lb = 0.f;
            #pragma unroll
            for (int r = 0; r < 16; ++r) {
                const float* src = &sbuf[(r * 14 + qq) * 8];
                la += src[ii];
                lb += src[4 + ii];
            }
            // fixed-point commit: exact integer adds -> order-independent
            const long long qa = llrintf(la * FPSCALE);
            const long long qb = llrintf(lb * FPSCALE);
            atomicAdd(&g_WIlin[t * W_DIM + tid], (unsigned long long)qa);
            atomicAdd(&g_WIsq [t * W_DIM + tid], (unsigned long long)qb);
        }
        __syncthreads();
    }
}

// ---------------------------------------------------------------------------
// Kernel 2: tiny epilogue. One block, 256 threads. Stages 42 KB into shared,
// RESETS the accumulators (so every launch/replay starts from zero), then
// 64 threads run the length-56 scans and tree-reduce to the scalar.
// ---------------------------------------------------------------------------
__global__ __launch_bounds__(256) void finish_kernel(float* __restrict__ out)
{
    const int tid = threadIdx.x;

    __shared__ float2 shW[T_DIM * W_DIM];
    __shared__ float2 shH[T_DIM * H_DIM];

    for (int p = tid; p < T_DIM * W_DIM; p += 256) {
        long long la = (long long)g_WIlin[p];
        long long lb = (long long)g_WIsq [p];
        shW[p] = make_float2((float)la * FPINV, (float)lb * FPINV);
        g_WIlin[p] = 0ull;                 // deterministic reset for next launch
        g_WIsq [p] = 0ull;
        shH[p] = g_H[p];
    }
    __syncthreads();

    __shared__ float shS[64];
    if (tid < 64) {
        const int t  = tid & 31;
        const int ax = tid >> 5;           // 0 = H, 1 = W
        const float2* __restrict__ s = (ax ? shW : shH) + t * 56;

        const float n_other = (float)(C_DIM) * 56.f;  // 28672
        float total = 0.f;

        float csq = 0.f, clin = 0.f;
        #pragma unroll
        for (int i = 55; i >= 0; --i) {    // suffix slices [i:]
            float2 v = s[i];
            clin += v.x;
            csq  += v.y;
            float n = n_other * (float)(56 - i);
            total += sqrtf(csq + 2.f * EPSF * clin + (EPSF * EPSF) * n) + EPSF;
        }
        csq = 0.f; clin = 0.f;
        #pragma unroll
        for (int i = 0; i < 56; ++i) {     // prefix slices [:j+1]
            float2 v = s[i];
            clin += v.x;
            csq  += v.y;
            float n = n_other * (float)(i + 1);
            total += sqrtf(csq + 2.f * EPSF * clin + (EPSF * EPSF) * n) + EPSF;
        }
        shS[tid] = total;
    }
    __syncthreads();
    if (tid < 32) {
        float v = shS[tid] + shS[tid + 32];
        #pragma unroll
        for (int off = 16; off > 0; off >>= 1)
            v += __shfl_down_sync(0xffffffffu, v, off);
        if (tid == 0) out[0] = v / 128.f;  // / (T=32 * 4 losses)
    }
}

// ---------------------------------------------------------------------------
extern "C" void kernel_launch(void* const* d_in, const int* in_sizes, int n_in,
                              void* d_out, int out_size)
{
    const float* x = (const float*)d_in[0];
    float* out = (float*)d_out;
    (void)in_sizes; (void)n_in; (void)out_size;

    reduce_kernel<<<GRID1, 224>>>(x);
    finish_kernel<<<1, 256>>>(out);
}